// round 1
// baseline (speedup 1.0000x reference)
#include <cuda_runtime.h>
#include <math.h>

#define Hh 160
#define Ww 160
#define Bb 4
#define Cc 64
#define Oo 64
#define KKp 9
#define NOC 192            // 64 folded pm + 128 qn rows
#define KTOT 576           // C * KK
#define TP 32              // pixels per block (along W)
#define KC 16              // k-chunk for GEMM staging
#define NTHREADS 128

// folded, k-major weight matrix: g_Wc[k][j], j in [0,192)
__device__ float g_Wc[KTOT * NOC];

// ---------------------------------------------------------------------------
// prep: build g_Wc.  j<64: w_m[j]+w_m[j+64] (pm fold);  j>=64: w_n[j-64]
// w_m/w_n layout: [128][576] (oc-major, k = c*9+kk contiguous)
// ---------------------------------------------------------------------------
__global__ void prep_kernel(const float* __restrict__ w_m,
                            const float* __restrict__ w_n) {
    int idx = blockIdx.x * blockDim.x + threadIdx.x;
    if (idx >= KTOT * NOC) return;
    int k = idx / NOC;
    int j = idx - k * NOC;
    float v;
    if (j < 64) v = w_m[j * KTOT + k] + w_m[(j + 64) * KTOT + k];
    else        v = w_n[(j - 64) * KTOT + k];
    g_Wc[idx] = v;
}

// ---------------------------------------------------------------------------
// main fused kernel
// ---------------------------------------------------------------------------
__global__ void __launch_bounds__(NTHREADS, 2)
pala_kernel(const float* __restrict__ x,
            const float* __restrict__ off_w,
            const float* __restrict__ off_b,
            const float* __restrict__ w0,
            float* __restrict__ out) {
    extern __shared__ float sm[];
    float* s_samp = sm;                    // [576][32]  18432 floats
    float* s_w    = sm + 18432;            // [16][192]   3072 floats (aliased as x-tile)
    float* s_geo  = sm + 18432 + 3072;     // 8 planes of [9][32]: 4 idx(int) + 4 weights
    float* s_off  = s_geo + 8 * 288;       // oy[9][32], ox[9][32]

    const int tid = threadIdx.x;
    const int w0i = blockIdx.x * TP;
    const int h   = blockIdx.y;
    const int b   = blockIdx.z;

    const float* xb = x + (size_t)b * Cc * Hh * Ww;

    // --- Phase A0: load x column tile [64 ch][32 px] into s_w scratch ---
    float* s_tmp = s_w;   // 2048 floats <= 3072
    for (int i = tid; i < Cc * TP; i += NTHREADS) {
        int c = i >> 5, p = i & 31;
        s_tmp[i] = xb[(c * Hh + h) * Ww + w0i + p];
    }
    __syncthreads();

    // --- Phase A1: offset conv (18 ch x 32 px) + clip + tanh soft-limit ---
    for (int i = tid; i < 18 * TP; i += NTHREADS) {
        int o = i >> 5, p = i & 31;
        float acc = off_b[o];
        const float* wrow = off_w + o * Cc;
        #pragma unroll 8
        for (int c = 0; c < Cc; c++)
            acc += wrow[c] * s_tmp[c * TP + p];
        float lo, hi;
        if ((o & 1) == 0) { lo = -(float)h;          hi = (float)(Hh - h); }
        else              { int gx = w0i + p; lo = -(float)gx; hi = (float)(Ww - gx); }
        float v = fminf(fmaxf(acc, lo), hi);
        if (fabsf(v) >= 8.0f) v = 8.0f * tanhf(v * 0.125f);
        int kk = o >> 1;
        s_off[((o & 1) * 288) + kk * TP + p] = v;   // oy then ox
    }
    __syncthreads();

    // --- Phase A2: per-(kk,pixel) bilinear geometry (288 tasks) ---
    for (int i = tid; i < 288; i += NTHREADS) {
        int kk = i >> 5, p = i & 31;
        float oy = s_off[i];
        float ox = s_off[288 + i];
        float py = (float)(h - 1 + kk / 3) + oy;
        float px = (float)(w0i + p - 1 + kk % 3) + ox;
        float y0f = floorf(py), x0f = floorf(px);
        float wy = py - y0f,   wx = px - x0f;
        int y0 = (int)y0f, x0 = (int)x0f;
        int y1 = y0 + 1,   x1 = x0 + 1;
        float vy0 = (y0 >= 0 && y0 < Hh) ? 1.f : 0.f;
        float vy1 = (y1 >= 0 && y1 < Hh) ? 1.f : 0.f;
        float vx0 = (x0 >= 0 && x0 < Ww) ? 1.f : 0.f;
        float vx1 = (x1 >= 0 && x1 < Ww) ? 1.f : 0.f;
        int cy0 = min(max(y0, 0), Hh - 1), cy1 = min(max(y1, 0), Hh - 1);
        int cx0 = min(max(x0, 0), Ww - 1), cx1 = min(max(x1, 0), Ww - 1);
        int* s_geoi = (int*)s_geo;
        s_geoi[0 * 288 + i] = cy0 * Ww + cx0;
        s_geoi[1 * 288 + i] = cy0 * Ww + cx1;
        s_geoi[2 * 288 + i] = cy1 * Ww + cx0;
        s_geoi[3 * 288 + i] = cy1 * Ww + cx1;
        s_geo[4 * 288 + i] = (1.f - wy) * (1.f - wx) * vy0 * vx0;
        s_geo[5 * 288 + i] = (1.f - wy) * wx         * vy0 * vx1;
        s_geo[6 * 288 + i] = wy * (1.f - wx)         * vy1 * vx0;
        s_geo[7 * 288 + i] = wy * wx                 * vy1 * vx1;
    }
    __syncthreads();

    // --- Phase B: deformable bilinear sampling -> s_samp[k = c*9+kk][p] ---
    const int wid = tid >> 5, lane = tid & 31;
    const int* s_geoi = (const int*)s_geo;
    for (int task = wid; task < KTOT; task += (NTHREADS / 32)) {
        int c  = task / 9;
        int kk = task - c * 9;
        int gi = kk * TP + lane;
        const float* xc = xb + c * (Hh * Ww);
        int i00 = s_geoi[0 * 288 + gi];
        int i01 = s_geoi[1 * 288 + gi];
        int i10 = s_geoi[2 * 288 + gi];
        int i11 = s_geoi[3 * 288 + gi];
        float g00 = s_geo[4 * 288 + gi], g01 = s_geo[5 * 288 + gi];
        float g10 = s_geo[6 * 288 + gi], g11 = s_geo[7 * 288 + gi];
        float v = g00 * __ldg(xc + i00) + g01 * __ldg(xc + i01)
                + g10 * __ldg(xc + i10) + g11 * __ldg(xc + i11);
        s_samp[task * TP + lane] = v;
    }
    // barrier comes from the first GEMM staging sync below

    // --- Phase C: register-tiled GEMM: acc[12 oc][4 px] per thread ---
    const int ocg = tid >> 3;        // 0..15
    const int pg  = tid & 7;         // 0..7
    const int oc0 = ocg * 12;
    const int p0  = pg * 4;
    float acc[12][4];
    #pragma unroll
    for (int i = 0; i < 12; i++)
        #pragma unroll
        for (int j = 0; j < 4; j++) acc[i][j] = 0.f;

    for (int kc = 0; kc < KTOT; kc += KC) {
        __syncthreads();   // (iter 0: closes phase B; later: protects s_w reuse)
        const float4* gw = (const float4*)(g_Wc + kc * NOC);
        float4* sw4 = (float4*)s_w;
        #pragma unroll
        for (int i = 0; i < (KC * NOC / 4) / NTHREADS; i++)
            sw4[tid + i * NTHREADS] = gw[tid + i * NTHREADS];
        __syncthreads();
        #pragma unroll
        for (int r = 0; r < KC; r++) {
            float4 sp = *(const float4*)(s_samp + (kc + r) * TP + p0);
            float4 wa = *(const float4*)(s_w + r * NOC + oc0);
            float4 wb = *(const float4*)(s_w + r * NOC + oc0 + 4);
            float4 wc = *(const float4*)(s_w + r * NOC + oc0 + 8);
            float wv[12] = {wa.x, wa.y, wa.z, wa.w,
                            wb.x, wb.y, wb.z, wb.w,
                            wc.x, wc.y, wc.z, wc.w};
            float sv[4] = {sp.x, sp.y, sp.z, sp.w};
            #pragma unroll
            for (int i = 0; i < 12; i++)
                #pragma unroll
                for (int j = 0; j < 4; j++)
                    acc[i][j] += wv[i] * sv[j];
        }
    }
    __syncthreads();   // everyone done reading s_samp before we overwrite it

    // --- stage results into s_samp as res[oc 0..191][p] ---
    #pragma unroll
    for (int i = 0; i < 12; i++)
        #pragma unroll
        for (int j = 0; j < 4; j++)
            s_samp[(oc0 + i) * TP + p0 + j] = acc[i][j];
    __syncthreads();

    // --- epilogue: (pm + w0) / (1 + |qa| + |qb|) ---
    for (int i = tid; i < Oo * TP; i += NTHREADS) {
        int c = i >> 5, p = i & 31;
        float pm = s_samp[c * TP + p];
        float qa = s_samp[(64 + c) * TP + p];
        float qb = s_samp[(128 + c) * TP + p];
        float r = (pm + w0[c]) / (1.0f + fabsf(qa) + fabsf(qb));
        out[(((size_t)b * Oo + c) * Hh + h) * Ww + w0i + p] = r;
    }
}

// ---------------------------------------------------------------------------
extern "C" void kernel_launch(void* const* d_in, const int* in_sizes, int n_in,
                              void* d_out, int out_size) {
    (void)in_sizes; (void)n_in; (void)out_size;
    const float* x     = (const float*)d_in[0];
    const float* off_w = (const float*)d_in[1];
    const float* off_b = (const float*)d_in[2];
    const float* w_m   = (const float*)d_in[3];
    const float* w_n   = (const float*)d_in[4];
    const float* w0    = (const float*)d_in[5];
    float* out = (float*)d_out;

    const int prep_n = KTOT * NOC;
    prep_kernel<<<(prep_n + 255) / 256, 256>>>(w_m, w_n);

    const int smem_bytes = (18432 + 3072 + 8 * 288 + 2 * 288) * 4;  // 97536
    cudaFuncSetAttribute(pala_kernel,
                         cudaFuncAttributeMaxDynamicSharedMemorySize, smem_bytes);
    dim3 grid(Ww / TP, Hh, Bb);
    pala_kernel<<<grid, NTHREADS, smem_bytes>>>(x, off_w, off_b, w0, out);
}

// round 3
// speedup vs baseline: 1.1407x; 1.1407x over previous
#include <cuda_runtime.h>
#include <cuda_bf16.h>
#include <stdint.h>
#include <math.h>

#define Hh 160
#define Ww 160
#define Bb 4
#define Cc 64
#define Oo 64
#define NOC 192            // 64 folded pm + 128 qn rows
#define KTOT 576           // k = c*9 + kk (natural order)
#define NTH 256
#define TP 32

// A (pixel) buffer: 32 rows, each: [hi 576 bf16][lo 576 bf16][pad] stride 2352B
#define A_STRIDE 2352
#define OFF_A 0
#define A_BYTES (32 * A_STRIDE)            // 75264
// weight chunk buffers: rows n (192), each [hi 32 bf16][lo 32 bf16][pad] 144B
#define OFF_B A_BYTES
#define B_STRIDE 144
#define B_BUF (NOC * B_STRIDE)             // 27648
#define SMEM_BYTES (OFF_B + 2 * B_BUF)     // 130560

// scratch aliases inside B region (dead before first weight chunk copy)
#define OFF_GEO  OFF_B                     // 8 planes x 288 x 4B = 9216
#define OFF_SOFF (OFF_B + 9216)            // 2 x 288 x 4B
#define OFF_SX   (OFF_B + 11520)           // 64 x 32 x 4B = 8192

__device__ __align__(16) __nv_bfloat16 g_Whi[NOC * KTOT];
__device__ __align__(16) __nv_bfloat16 g_Wlo[NOC * KTOT];

// ---------------------------------------------------------------------------
__device__ __forceinline__ uint32_t smem_u32(const void* p) {
    uint32_t a;
    asm("{ .reg .u64 t; cvta.to.shared.u64 t, %1; cvt.u32.u64 %0, t; }"
        : "=r"(a) : "l"(p));
    return a;
}
__device__ __forceinline__ void ldsm4(uint32_t* r, uint32_t a) {
    asm volatile("ldmatrix.sync.aligned.m8n8.x4.shared.b16 {%0,%1,%2,%3}, [%4];"
        : "=r"(r[0]), "=r"(r[1]), "=r"(r[2]), "=r"(r[3]) : "r"(a));
}
__device__ __forceinline__ void ldsm2(uint32_t* r, uint32_t a) {
    asm volatile("ldmatrix.sync.aligned.m8n8.x2.shared.b16 {%0,%1}, [%2];"
        : "=r"(r[0]), "=r"(r[1]) : "r"(a));
}
__device__ __forceinline__ void mma16816(float* d, const uint32_t* a,
                                         const uint32_t* b) {
    asm volatile("mma.sync.aligned.m16n8k16.row.col.f32.bf16.bf16.f32 "
        "{%0,%1,%2,%3}, {%4,%5,%6,%7}, {%8,%9}, {%0,%1,%2,%3};"
        : "+f"(d[0]), "+f"(d[1]), "+f"(d[2]), "+f"(d[3])
        : "r"(a[0]), "r"(a[1]), "r"(a[2]), "r"(a[3]), "r"(b[0]), "r"(b[1]));
}

// ---------------------------------------------------------------------------
// prep: fold + bf16-split weights, layout [n][k] row-major, k natural
// ---------------------------------------------------------------------------
__global__ void prep_kernel(const float* __restrict__ w_m,
                            const float* __restrict__ w_n) {
    int idx = blockIdx.x * blockDim.x + threadIdx.x;
    if (idx >= NOC * KTOT) return;
    int n = idx / KTOT;
    int k = idx - n * KTOT;
    float v;
    if (n < 64) v = w_m[n * KTOT + k] + w_m[(n + 64) * KTOT + k];
    else        v = w_n[(n - 64) * KTOT + k];
    __nv_bfloat16 h = __float2bfloat16(v);
    g_Whi[idx] = h;
    g_Wlo[idx] = __float2bfloat16(v - __bfloat162float(h));
}

// ---------------------------------------------------------------------------
// fused kernel: one CTA = 32 px (one h row, 32 w) x 192 output rows
// ---------------------------------------------------------------------------
__global__ void __launch_bounds__(NTH)
pala_mma_kernel(const float* __restrict__ x,
                const float* __restrict__ off_w,
                const float* __restrict__ off_b,
                const float* __restrict__ w0v,
                float* __restrict__ out) {
    extern __shared__ char sm[];
    const uint32_t sb = smem_u32(sm);
    const int tid = threadIdx.x, wid = tid >> 5, lane = tid & 31;
    const int w0i = blockIdx.x * TP;
    const int h = blockIdx.y;
    const int b = blockIdx.z;
    const float* xb = x + (size_t)b * (Cc * Hh * Ww);

    // --- Phase A0: stage x column tile [64c][32px] ---
    float* s_x = (float*)(sm + OFF_SX);
    for (int i = tid; i < Cc * TP; i += NTH) {
        int c = i >> 5, p = i & 31;
        s_x[i] = xb[(c * Hh + h) * Ww + w0i + p];
    }
    __syncthreads();

    // --- Phase A1: offset 1x1 conv + clip + tanh soft limit ---
    float* s_off = (float*)(sm + OFF_SOFF);      // [2][9][32]
    for (int i = tid; i < 18 * TP; i += NTH) {
        int o = i >> 5, p = i & 31;
        float acc = off_b[o];
        const float* wr = off_w + o * Cc;
        #pragma unroll 8
        for (int c = 0; c < Cc; c++) acc += wr[c] * s_x[c * TP + p];
        float lo, hi;
        if ((o & 1) == 0) { lo = -(float)h; hi = (float)(Hh - h); }
        else              { int gx = w0i + p; lo = -(float)gx; hi = (float)(Ww - gx); }
        float v = fminf(fmaxf(acc, lo), hi);
        if (fabsf(v) >= 8.0f) v = 8.0f * tanhf(v * 0.125f);
        s_off[(o & 1) * 288 + (o >> 1) * TP + p] = v;
    }
    __syncthreads();

    // --- Phase A2: bilinear geometry: 4 clamped indices + 4 folded weights ---
    int*   gI = (int*)(sm + OFF_GEO);
    float* gF = (float*)(sm + OFF_GEO);
    for (int i = tid; i < 288; i += NTH) {
        int kk = i >> 5, p = i & 31;
        float oy = s_off[i];
        float ox = s_off[288 + i];
        float py = (float)(h - 1 + kk / 3) + oy;
        float px = (float)(w0i + p - 1 + kk % 3) + ox;
        float y0f = floorf(py), x0f = floorf(px);
        float wy = py - y0f, wx = px - x0f;
        int y0 = (int)y0f, x0 = (int)x0f;
        int y1 = y0 + 1, x1 = x0 + 1;
        float vy0 = (y0 >= 0 && y0 < Hh) ? 1.f : 0.f;
        float vy1 = (y1 >= 0 && y1 < Hh) ? 1.f : 0.f;
        float vx0 = (x0 >= 0 && x0 < Ww) ? 1.f : 0.f;
        float vx1 = (x1 >= 0 && x1 < Ww) ? 1.f : 0.f;
        int cy0 = min(max(y0, 0), Hh - 1), cy1 = min(max(y1, 0), Hh - 1);
        int cx0 = min(max(x0, 0), Ww - 1), cx1 = min(max(x1, 0), Ww - 1);
        gI[0 * 288 + i] = cy0 * Ww + cx0;
        gI[1 * 288 + i] = cy0 * Ww + cx1;
        gI[2 * 288 + i] = cy1 * Ww + cx0;
        gI[3 * 288 + i] = cy1 * Ww + cx1;
        gF[4 * 288 + i] = (1.f - wy) * (1.f - wx) * vy0 * vx0;
        gF[5 * 288 + i] = (1.f - wy) * wx         * vy0 * vx1;
        gF[6 * 288 + i] = wy * (1.f - wx)         * vy1 * vx0;
        gF[7 * 288 + i] = wy * wx                 * vy1 * vx1;
    }
    __syncthreads();

    // --- Phase B: bilinear sampling -> A[px][k] bf16 hi/lo ---
    for (int t = wid; t < KTOT; t += 8) {
        int c = t / 9;
        int kk = t - c * 9;
        int gi = kk * TP + lane;
        const float* xc = xb + c * (Hh * Ww);
        int i00 = gI[gi],            i01 = gI[288 + gi];
        int i10 = gI[2 * 288 + gi],  i11 = gI[3 * 288 + gi];
        float g00 = gF[4 * 288 + gi], g01 = gF[5 * 288 + gi];
        float g10 = gF[6 * 288 + gi], g11 = gF[7 * 288 + gi];
        float v = g00 * __ldg(xc + i00) + g01 * __ldg(xc + i01)
                + g10 * __ldg(xc + i10) + g11 * __ldg(xc + i11);
        __nv_bfloat16 hbf = __float2bfloat16(v);
        __nv_bfloat16 lbf = __float2bfloat16(v - __bfloat162float(hbf));
        char* row = sm + OFF_A + lane * A_STRIDE;
        *(__nv_bfloat16*)(row + 2 * t) = hbf;
        *(__nv_bfloat16*)(row + 1152 + 2 * t) = lbf;
    }
    __syncthreads();   // sampling done; scratch (geo etc.) now dead

    // --- Phase C: warp-MMA GEMM, K chunks of 32, double-buffered weights ---
    // warp w: n0 = w*24 (3 n-tiles of 8), both m-tiles (32 px)
    const int n0 = wid * 24;
    const int grp = lane >> 3;
    // A frag addresses (per thread): row/k-offset pattern for ldmatrix.x4
    const int aRow = (grp & 1) * 8 + (lane & 7);
    const int aK8 = (grp >> 1) * 8;
    // B x4 (tiles 0,1) and x2 (tile 2) address patterns
    const int b4Row = n0 + (grp >> 1) * 8 + (lane & 7);
    const int b4K8 = (grp & 1) * 8;
    const int l16 = lane & 15;
    const int b2Row = n0 + 16 + (l16 & 7);
    const int b2K8 = (l16 >> 3) * 8;

    float acc[2][3][4];
    #pragma unroll
    for (int mt = 0; mt < 2; mt++)
        #pragma unroll
        for (int j = 0; j < 3; j++)
            #pragma unroll
            for (int q = 0; q < 4; q++) acc[mt][j][q] = 0.f;

    // prologue: copy weight chunk 0 into buf 0
    {
        for (int u = 0; u < 6; u++) {
            int i = tid + u * NTH;           // 0..1535
            int half = (i >= 768);
            int r = half ? i - 768 : i;
            int n = r >> 2, q = r & 3;
            const __nv_bfloat16* src = (half ? g_Wlo : g_Whi) + n * KTOT + q * 8;
            uint4 v = *(const uint4*)src;
            *(uint4*)(sm + OFF_B + n * B_STRIDE + half * 64 + q * 16) = v;
        }
    }
    __syncthreads();

    for (int ck = 0; ck < 18; ck++) {
        // issue next chunk's global loads early (hide L2 latency)
        uint4 cp[6];
        if (ck < 17) {
            int kb = (ck + 1) * 32;
            #pragma unroll
            for (int u = 0; u < 6; u++) {
                int i = tid + u * NTH;
                int half = (i >= 768);
                int r = half ? i - 768 : i;
                int n = r >> 2, q = r & 3;
                cp[u] = *(const uint4*)((half ? g_Wlo : g_Whi)
                                        + n * KTOT + kb + q * 8);
            }
        }

        const uint32_t bufB = sb + OFF_B + (uint32_t)(ck & 1) * B_BUF;
        #pragma unroll
        for (int s = 0; s < 2; s++) {
            const int k0 = ck * 32 + s * 16;
            const int ks = s * 16;
            uint32_t af[2][2][4];
            #pragma unroll
            for (int mt = 0; mt < 2; mt++) {
                uint32_t base = sb + OFF_A + (uint32_t)((mt * 16 + aRow) * A_STRIDE);
                ldsm4(af[mt][0], base + 2 * (k0 + aK8));          // hi
                ldsm4(af[mt][1], base + 1152 + 2 * (k0 + aK8));   // lo
            }
            uint32_t b01[2][4], b2[2][2];
            #pragma unroll
            for (int hl = 0; hl < 2; hl++) {
                ldsm4(b01[hl], bufB + b4Row * B_STRIDE + hl * 64 + 2 * (ks + b4K8));
                ldsm2(b2[hl],  bufB + b2Row * B_STRIDE + hl * 64 + 2 * (ks + b2K8));
            }
            #pragma unroll
            for (int mt = 0; mt < 2; mt++) {
                #pragma unroll
                for (int j = 0; j < 3; j++) {
                    const uint32_t* bh = (j < 2) ? &b01[0][j * 2] : b2[0];
                    const uint32_t* bl = (j < 2) ? &b01[1][j * 2] : b2[1];
                    mma16816(acc[mt][j], af[mt][0], bh);   // hi*hi
                    mma16816(acc[mt][j], af[mt][1], bh);   // lo*hi
                    mma16816(acc[mt][j], af[mt][0], bl);   // hi*lo
                }
            }
        }

        if (ck < 17) {
            char* dst = sm + OFF_B + ((ck + 1) & 1) * B_BUF;
            #pragma unroll
            for (int u = 0; u < 6; u++) {
                int i = tid + u * NTH;
                int half = (i >= 768);
                int r = half ? i - 768 : i;
                int n = r >> 2, q = r & 3;
                *(uint4*)(dst + n * B_STRIDE + half * 64 + q * 16) = cp[u];
            }
        }
        __syncthreads();
    }

    // --- stage accumulators to smem res[n][m], stride 33 floats ---
    float* res = (float*)(sm + OFF_B);
    {
        const int g = lane >> 2, tig = lane & 3;
        #pragma unroll
        for (int mt = 0; mt < 2; mt++) {
            #pragma unroll
            for (int j = 0; j < 3; j++) {
                int nb = n0 + j * 8 + tig * 2;
                int mb = mt * 16 + g;
                res[nb * 33 + mb]           = acc[mt][j][0];
                res[(nb + 1) * 33 + mb]     = acc[mt][j][1];
                res[nb * 33 + mb + 8]       = acc[mt][j][2];
                res[(nb + 1) * 33 + mb + 8] = acc[mt][j][3];
            }
        }
    }
    __syncthreads();

    // --- epilogue: (pm + w0) / (1 + |qa| + |qb|) ---
    for (int i = tid; i < Oo * TP; i += NTH) {
        int c = i >> 5, p = i & 31;
        float pm = res[c * 33 + p] + __ldg(w0v + c);
        float den = 1.0f + fabsf(res[(64 + c) * 33 + p])
                         + fabsf(res[(128 + c) * 33 + p]);
        out[(((size_t)b * Oo + c) * Hh + h) * Ww + w0i + p] = pm / den;
    }
}

// ---------------------------------------------------------------------------
extern "C" void kernel_launch(void* const* d_in, const int* in_sizes, int n_in,
                              void* d_out, int out_size) {
    (void)in_sizes; (void)n_in; (void)out_size;
    const float* x     = (const float*)d_in[0];
    const float* off_w = (const float*)d_in[1];
    const float* off_b = (const float*)d_in[2];
    const float* w_m   = (const float*)d_in[3];
    const float* w_n   = (const float*)d_in[4];
    const float* w0    = (const float*)d_in[5];
    float* out = (float*)d_out;

    prep_kernel<<<(NOC * KTOT + 255) / 256, 256>>>(w_m, w_n);

    cudaFuncSetAttribute(pala_mma_kernel,
                         cudaFuncAttributeMaxDynamicSharedMemorySize, SMEM_BYTES);
    dim3 grid(Ww / TP, Hh, Bb);
    pala_mma_kernel<<<grid, NTH, SMEM_BYTES>>>(x, off_w, off_b, w0, out);
}

// round 7
// speedup vs baseline: 1.5496x; 1.3585x over previous
#include <cuda_runtime.h>
#include <cuda_bf16.h>
#include <stdint.h>
#include <math.h>

#define Hh 160
#define Ww 160
#define Bb 4
#define Cc 64
#define Oo 64
#define NOC 192            // 64 folded pm + 128 qn rows
#define KTOT 576           // k = c*9 + kk (natural order)
#define NTH 256
#define TP 32
#define NCHUNK 36          // K chunks of 16

// A (pixel) buffer: 32 rows, [hi 576 bf16][lo 576 bf16][pad] stride 2352B
#define A_STRIDE 2352
#define OFF_A 0
#define A_BYTES (32 * A_STRIDE)            // 75264
// per-warp B rings: 8 warps x 2 bufs x (24 rows x 80B) = 30720
#define OFF_B A_BYTES
#define B_ROWB 80
#define B_BUFW (24 * B_ROWB)               // 1920 per warp per buf
#define SMEM_BYTES (OFF_B + 8 * 2 * B_BUFW)   // 105984

// scratch aliases inside B region (dead before first cp.async)
#define OFF_GEO  OFF_B                     // 8 planes x 288 x 4B = 9216
#define OFF_SOFF (OFF_B + 9216)            // 2 x 288 x 4B = 2304
#define OFF_SX   (OFF_B + 11520)           // 64 x 32 x 4B = 8192

__device__ __align__(16) __nv_bfloat16 g_Whi[NOC * KTOT];
__device__ __align__(16) __nv_bfloat16 g_Wlo[NOC * KTOT];

// ---------------------------------------------------------------------------
__device__ __forceinline__ uint32_t smem_u32(const void* p) {
    uint32_t a;
    asm("{ .reg .u64 t; cvta.to.shared.u64 t, %1; cvt.u32.u64 %0, t; }"
        : "=r"(a) : "l"(p));
    return a;
}
__device__ __forceinline__ void ldsm4(uint32_t* r, uint32_t a) {
    asm volatile("ldmatrix.sync.aligned.m8n8.x4.shared.b16 {%0,%1,%2,%3}, [%4];"
        : "=r"(r[0]), "=r"(r[1]), "=r"(r[2]), "=r"(r[3]) : "r"(a));
}
__device__ __forceinline__ void ldsm2(uint32_t* r, uint32_t a) {
    asm volatile("ldmatrix.sync.aligned.m8n8.x2.shared.b16 {%0,%1}, [%2];"
        : "=r"(r[0]), "=r"(r[1]) : "r"(a));
}
__device__ __forceinline__ void mma16816(float* d, const uint32_t* a,
                                         const uint32_t* b) {
    asm volatile("mma.sync.aligned.m16n8k16.row.col.f32.bf16.bf16.f32 "
        "{%0,%1,%2,%3}, {%4,%5,%6,%7}, {%8,%9}, {%0,%1,%2,%3};"
        : "+f"(d[0]), "+f"(d[1]), "+f"(d[2]), "+f"(d[3])
        : "r"(a[0]), "r"(a[1]), "r"(a[2]), "r"(a[3]), "r"(b[0]), "r"(b[1]));
}
#define CP_ASYNC16(dst, src) \
    asm volatile("cp.async.ca.shared.global [%0], [%1], 16;" \
                 :: "r"(dst), "l"(src) : "memory")
#define CP_COMMIT() asm volatile("cp.async.commit_group;" ::: "memory")
#define CP_WAIT1()  asm volatile("cp.async.wait_group 1;" ::: "memory")
#define CP_WAIT0()  asm volatile("cp.async.wait_group 0;" ::: "memory")

// ---------------------------------------------------------------------------
// prep: fold + bf16-split weights, layout [n][k] row-major, k natural
// ---------------------------------------------------------------------------
__global__ void prep_kernel(const float* __restrict__ w_m,
                            const float* __restrict__ w_n) {
    int idx = blockIdx.x * blockDim.x + threadIdx.x;
    if (idx >= NOC * KTOT) return;
    int n = idx / KTOT;
    int k = idx - n * KTOT;
    float v;
    if (n < 64) v = w_m[n * KTOT + k] + w_m[(n + 64) * KTOT + k];
    else        v = w_n[(n - 64) * KTOT + k];
    __nv_bfloat16 h = __float2bfloat16(v);
    g_Whi[idx] = h;
    g_Wlo[idx] = __float2bfloat16(v - __bfloat162float(h));
}

// ---------------------------------------------------------------------------
// fused kernel: one CTA = 32 px (one h row, 32 w) x 192 output rows
// ---------------------------------------------------------------------------
__global__ void __launch_bounds__(NTH, 2)
pala_mma_kernel(const float* __restrict__ x,
                const float* __restrict__ off_w,
                const float* __restrict__ off_b,
                const float* __restrict__ w0v,
                float* __restrict__ out) {
    extern __shared__ char sm[];
    const uint32_t sb = smem_u32(sm);
    const int tid = threadIdx.x, wid = tid >> 5, lane = tid & 31;
    const int w0i = blockIdx.x * TP;
    const int h = blockIdx.y;
    const int b = blockIdx.z;
    const float* xb = x + (size_t)b * (Cc * Hh * Ww);

    // --- Phase A0: stage x column tile [64c][32px] ---
    float* s_x = (float*)(sm + OFF_SX);
    for (int i = tid; i < Cc * TP; i += NTH) {
        int c = i >> 5, p = i & 31;
        s_x[i] = xb[(c * Hh + h) * Ww + w0i + p];
    }
    __syncthreads();

    // --- Phase A1: offset 1x1 conv + clip + tanh soft limit ---
    float* s_off = (float*)(sm + OFF_SOFF);      // [2][9][32]
    for (int i = tid; i < 18 * TP; i += NTH) {
        int o = i >> 5, p = i & 31;
        float acc = off_b[o];
        const float* wr = off_w + o * Cc;
        #pragma unroll 8
        for (int c = 0; c < Cc; c++) acc += wr[c] * s_x[c * TP + p];
        float lo, hi;
        if ((o & 1) == 0) { lo = -(float)h; hi = (float)(Hh - h); }
        else              { int gx = w0i + p; lo = -(float)gx; hi = (float)(Ww - gx); }
        float v = fminf(fmaxf(acc, lo), hi);
        if (fabsf(v) >= 8.0f) v = 8.0f * tanhf(v * 0.125f);
        s_off[(o & 1) * 288 + (o >> 1) * TP + p] = v;
    }
    __syncthreads();

    // --- Phase A2: bilinear geometry: 4 clamped indices + 4 folded weights ---
    int*   gI = (int*)(sm + OFF_GEO);
    float* gF = (float*)(sm + OFF_GEO);
    for (int i = tid; i < 288; i += NTH) {
        int kk = i >> 5, p = i & 31;
        float oy = s_off[i];
        float ox = s_off[288 + i];
        float py = (float)(h - 1 + kk / 3) + oy;
        float px = (float)(w0i + p - 1 + kk % 3) + ox;
        float y0f = floorf(py), x0f = floorf(px);
        float wy = py - y0f, wx = px - x0f;
        int y0 = (int)y0f, x0 = (int)x0f;
        int y1 = y0 + 1, x1 = x0 + 1;
        float vy0 = (y0 >= 0 && y0 < Hh) ? 1.f : 0.f;
        float vy1 = (y1 >= 0 && y1 < Hh) ? 1.f : 0.f;
        float vx0 = (x0 >= 0 && x0 < Ww) ? 1.f : 0.f;
        float vx1 = (x1 >= 0 && x1 < Ww) ? 1.f : 0.f;
        int cy0 = min(max(y0, 0), Hh - 1), cy1 = min(max(y1, 0), Hh - 1);
        int cx0 = min(max(x0, 0), Ww - 1), cx1 = min(max(x1, 0), Ww - 1);
        gI[0 * 288 + i] = cy0 * Ww + cx0;
        gI[1 * 288 + i] = cy0 * Ww + cx1;
        gI[2 * 288 + i] = cy1 * Ww + cx0;
        gI[3 * 288 + i] = cy1 * Ww + cx1;
        gF[4 * 288 + i] = (1.f - wy) * (1.f - wx) * vy0 * vx0;
        gF[5 * 288 + i] = (1.f - wy) * wx         * vy0 * vx1;
        gF[6 * 288 + i] = wy * (1.f - wx)         * vy1 * vx0;
        gF[7 * 288 + i] = wy * wx                 * vy1 * vx1;
    }
    __syncthreads();

    // --- Phase B: bilinear sampling -> A[px][k] bf16 hi/lo ---
    #pragma unroll 2
    for (int t = wid; t < KTOT; t += 8) {
        int c = t / 9;
        int kk = t - c * 9;
        int gi = kk * TP + lane;
        const float* xc = xb + c * (Hh * Ww);
        int i00 = gI[gi],            i01 = gI[288 + gi];
        int i10 = gI[2 * 288 + gi],  i11 = gI[3 * 288 + gi];
        float g00 = gF[4 * 288 + gi], g01 = gF[5 * 288 + gi];
        float g10 = gF[6 * 288 + gi], g11 = gF[7 * 288 + gi];
        float v = g00 * __ldg(xc + i00) + g01 * __ldg(xc + i01)
                + g10 * __ldg(xc + i10) + g11 * __ldg(xc + i11);
        __nv_bfloat16 hbf = __float2bfloat16(v);
        __nv_bfloat16 lbf = __float2bfloat16(v - __bfloat162float(hbf));
        char* row = sm + OFF_A + lane * A_STRIDE;
        *(__nv_bfloat16*)(row + 2 * t) = hbf;
        *(__nv_bfloat16*)(row + 1152 + 2 * t) = lbf;
    }
    __syncthreads();   // A complete; geo scratch (B region) now dead

    // --- Phase C: warp-independent MMA GEMM, KC=16, per-warp cp.async ring ---
    const int n0 = wid * 24;
    const int grp = lane >> 3;
    const int aRow = (grp & 1) * 8 + (lane & 7);
    const int aK8 = (grp >> 1) * 8;
    const int b4off = ((grp >> 1) * 8 + (lane & 7)) * B_ROWB + (grp & 1) * 16;
    const int l16 = lane & 15;
    const int b2off = (16 + (l16 & 7)) * B_ROWB + (l16 >> 3) * 16;
    const uint32_t warpB = sb + OFF_B + (uint32_t)wid * (2 * B_BUFW);

    // cp.async one KC=16 chunk of this warp's 24 B rows (hi+lo) into buf
    #define CP_CHUNK(ck, buf) do { \
        _Pragma("unroll") \
        for (int u = 0; u < 3; u++) { \
            int i = lane + 32 * u; \
            int nl = i >> 2, q = i & 3, half = q >> 1, qq = q & 1; \
            const __nv_bfloat16* src = (half ? g_Wlo : g_Whi) \
                + (n0 + nl) * KTOT + (ck) * 16 + qq * 8; \
            uint32_t dst = warpB + (buf) * B_BUFW + nl * B_ROWB \
                         + half * 32 + qq * 16; \
            CP_ASYNC16(dst, src); \
        } \
        CP_COMMIT(); \
    } while (0)

    float acc[2][3][4];
    #pragma unroll
    for (int mt = 0; mt < 2; mt++)
        #pragma unroll
        for (int j = 0; j < 3; j++)
            #pragma unroll
            for (int q = 0; q < 4; q++) acc[mt][j][q] = 0.f;

    CP_CHUNK(0, 0);
    CP_CHUNK(1, 1);

    for (int ck = 0; ck < NCHUNK; ck++) {
        if (ck == NCHUNK - 1) { CP_WAIT0(); } else { CP_WAIT1(); }
        __syncwarp();
        const uint32_t bufB = warpB + (uint32_t)(ck & 1) * B_BUFW;
        const int k0 = ck * 16;

        uint32_t af[2][2][4];
        #pragma unroll
        for (int mt = 0; mt < 2; mt++) {
            uint32_t base = sb + OFF_A + (uint32_t)((mt * 16 + aRow) * A_STRIDE);
            ldsm4(af[mt][0], base + 2 * (k0 + aK8));          // hi
            ldsm4(af[mt][1], base + 1152 + 2 * (k0 + aK8));   // lo
        }
        uint32_t b01[2][4], b2[2][2];
        #pragma unroll
        for (int hl = 0; hl < 2; hl++) {
            ldsm4(b01[hl], bufB + b4off + hl * 32);
            ldsm2(b2[hl],  bufB + b2off + hl * 32);
        }
        #pragma unroll
        for (int mt = 0; mt < 2; mt++) {
            #pragma unroll
            for (int j = 0; j < 3; j++) {
                const uint32_t* bh = (j < 2) ? &b01[0][j * 2] : b2[0];
                const uint32_t* bl = (j < 2) ? &b01[1][j * 2] : b2[1];
                mma16816(acc[mt][j], af[mt][0], bh);   // hi*hi
                mma16816(acc[mt][j], af[mt][1], bh);   // lo*hi
                mma16816(acc[mt][j], af[mt][0], bl);   // hi*lo
            }
        }
        // refill the slot just consumed; MMAs above already drained its ldsm reads
        if (ck < NCHUNK - 2) CP_CHUNK(ck + 2, ck & 1);
    }
    __syncthreads();   // all warps done with B region before res staging

    // --- stage accumulators to smem res[n][m], stride 33 floats ---
    float* res = (float*)(sm + OFF_B);
    {
        const int g = lane >> 2, tig = lane & 3;
        #pragma unroll
        for (int mt = 0; mt < 2; mt++) {
            #pragma unroll
            for (int j = 0; j < 3; j++) {
                int nb = n0 + j * 8 + tig * 2;
                int mb = mt * 16 + g;
                res[nb * 33 + mb]           = acc[mt][j][0];
                res[(nb + 1) * 33 + mb]     = acc[mt][j][1];
                res[nb * 33 + mb + 8]       = acc[mt][j][2];
                res[(nb + 1) * 33 + mb + 8] = acc[mt][j][3];
            }
        }
    }
    __syncthreads();

    // --- epilogue: (pm + w0) / (1 + |qa| + |qb|) ---
    for (int i = tid; i < Oo * TP; i += NTH) {
        int c = i >> 5, p = i & 31;
        float pm = res[c * 33 + p] + __ldg(w0v + c);
        float den = 1.0f + fabsf(res[(64 + c) * 33 + p])
                         + fabsf(res[(128 + c) * 33 + p]);
        out[(((size_t)b * Oo + c) * Hh + h) * Ww + w0i + p] = pm / den;
    }
    #undef CP_CHUNK
}

// ---------------------------------------------------------------------------
extern "C" void kernel_launch(void* const* d_in, const int* in_sizes, int n_in,
                              void* d_out, int out_size) {
    (void)in_sizes; (void)n_in; (void)out_size;
    const float* x     = (const float*)d_in[0];
    const float* off_w = (const float*)d_in[1];
    const float* off_b = (const float*)d_in[2];
    const float* w_m   = (const float*)d_in[3];
    const float* w_n   = (const float*)d_in[4];
    const float* w0    = (const float*)d_in[5];
    float* out = (float*)d_out;

    prep_kernel<<<(NOC * KTOT + 255) / 256, 256>>>(w_m, w_n);

    cudaFuncSetAttribute(pala_mma_kernel,
                         cudaFuncAttributeMaxDynamicSharedMemorySize, SMEM_BYTES);
    dim3 grid(Ww / TP, Hh, Bb);
    pala_mma_kernel<<<grid, NTH, SMEM_BYTES>>>(x, off_w, off_b, w0, out);
}